// round 14
// baseline (speedup 1.0000x reference)
#include <cuda_runtime.h>
#include <math_constants.h>

// FusedScaleMaskSoftmax: x[2,16,2048,2048] fp32 -> causal-masked softmax (last dim).
//
// R13: R12's two-phase PDL split (softmax primary, zero-fill secondary) with
// SPLIT-PAIR WARP BALANCING in both kernels.
// Row pair (j, 2047-j) has EXACTLY 257 valid 32B chunks (CL+CH = 257 for all j)
// and 255 masked-tail chunks. The pair's two warps each process half of the
// pair's combined chunk list instead of one whole row each:
//   - every warp in the grid does identical work (~129 chunks, 5 iters max)
//     vs the old worst case of 256 chunks / 8 iters (2x CTA critical path).
//   - per-warp live chunks drop 8 -> 5 (40 payload regs) -> better packing.
// Kernel B adds ONE balanced __syncthreads to combine the two warps' partial
// row sums via 4 smem floats. Chunk coverage stays exact/disjoint with A.

#define SK        2048
#define THREADS   256            // 8 warps = 4 pairs per CTA
#define PAIRS_PC  4
#define NB        5              // max chunk slots per warp (ceil(129/32))
#define NA        4              // zero-fill iters (ceil(128/32))

__device__ __forceinline__ float ex2_approx(float x) {
    float r;
    asm("ex2.approx.ftz.f32 %0, %1;" : "=f"(r) : "f"(x));
    return r;
}

__device__ __forceinline__ void ldg256_cs(const float* p, float* v) {
    unsigned u0, u1, u2, u3, u4, u5, u6, u7;
    asm volatile("ld.global.cs.v8.b32 {%0,%1,%2,%3,%4,%5,%6,%7}, [%8];"
        : "=r"(u0), "=r"(u1), "=r"(u2), "=r"(u3),
          "=r"(u4), "=r"(u5), "=r"(u6), "=r"(u7)
        : "l"(p));
    v[0] = __uint_as_float(u0); v[1] = __uint_as_float(u1);
    v[2] = __uint_as_float(u2); v[3] = __uint_as_float(u3);
    v[4] = __uint_as_float(u4); v[5] = __uint_as_float(u5);
    v[6] = __uint_as_float(u6); v[7] = __uint_as_float(u7);
}

__device__ __forceinline__ void stg256(float* p, const float* v) {
    asm volatile("st.global.v8.b32 [%0], {%1,%2,%3,%4,%5,%6,%7,%8};"
        :: "l"(p),
           "r"(__float_as_uint(v[0])), "r"(__float_as_uint(v[1])),
           "r"(__float_as_uint(v[2])), "r"(__float_as_uint(v[3])),
           "r"(__float_as_uint(v[4])), "r"(__float_as_uint(v[5])),
           "r"(__float_as_uint(v[6])), "r"(__float_as_uint(v[7]))
        : "memory");
}

// ---------------- Kernel A: zero-fill of masked tail chunks (PDL secondary) ----
// Pair (j, 2047-j): tails are [CL,256) of rowL and [CH,256) of rowH,
// 255 chunks total. Each of the pair's two warps writes ~half.
__global__ __launch_bounds__(THREADS)
void causal_zero_tail(float* __restrict__ out) {
    const int wid = threadIdx.x >> 5;
    const int lid = threadIdx.x & 31;

    const unsigned P = blockIdx.x * PAIRS_PC + (wid >> 1); // pair id, 0..32767
    const int h = wid & 1;

    const unsigned m = P >> 10;            // matrix 0..31
    const int j = (int)(P & 1023u);
    const unsigned rowL = (m << 11) + j;
    const unsigned rowH = (m << 11) + (SK - 1 - j);
    const int CL = (j >> 3) + 1;           // ceil((j+1)/8)
    const int CH = 256 - (j >> 3);         // ceil((2048-j)/8)
    const int TA = 256 - CL;               // tail chunks of rowL
    const int T  = 255;                    // TA + (256-CH), constant
    const int S  = 128;                    // warp0 gets [0,128), warp1 [128,255)
    const int u0 = h ? S : 0;
    const int u1 = h ? T : S;

    float* __restrict__ yL = out + (size_t)rowL * SK;
    float* __restrict__ yH = out + (size_t)rowH * SK;
    const float z[8] = {0.f, 0.f, 0.f, 0.f, 0.f, 0.f, 0.f, 0.f};

    #pragma unroll
    for (int it = 0; it < NA; it++) {
        const int u = u0 + it * 32 + lid;
        if (u < u1) {
            const bool isL = (u < TA);
            const int  c   = isL ? (CL + u) : (CH + (u - TA));
            float* dst = (isL ? yL : yH) + (c << 3);
            stg256(dst, z);
        }
    }
}

// ---------------- Kernel B: softmax over valid chunks (PDL primary) ----------
// Pair's valid chunks: [0,CL) of rowL + [0,CH) of rowH = 257 total.
// Warp h takes virtual range [h?129:0, h?257:129). One balanced __syncthreads
// combines the two warps' partial row sums (4 smem floats per pair).
__global__ __launch_bounds__(THREADS)
void causal_softmax_prefix(const float* __restrict__ x,
                           float* __restrict__ out) {
    // Nothing in kernel A depends on B: release the PDL gate immediately.
    cudaTriggerProgrammaticLaunchCompletion();

    const float C = 0.08838834764831845f * 1.4426950408889634f;  // SCALE*log2(e)

    const int wid = threadIdx.x >> 5;
    const int lid = threadIdx.x & 31;
    const int pw  = wid >> 1;              // pair slot in CTA, 0..3
    const int h   = wid & 1;

    const unsigned P = blockIdx.x * PAIRS_PC + pw;   // pair id
    const unsigned m = P >> 10;
    const int j = (int)(P & 1023u);
    const unsigned rowL = (m << 11) + j;
    const unsigned rowH = (m << 11) + (SK - 1 - j);
    const int LL = j + 1;
    const int LH = SK - j;
    const int CL = (j >> 3) + 1;
    const int T  = 257;                    // CL + CH, constant for all j
    const int S  = 129;
    const int u0 = h ? S : 0;
    const int u1 = h ? T : S;

    const float* __restrict__ xL = x + (size_t)rowL * SK;
    const float* __restrict__ xH = x + (size_t)rowH * SK;
    float* __restrict__ yL = out + (size_t)rowL * SK;
    float* __restrict__ yH = out + (size_t)rowH * SK;

    float v[NB][8];

    // ---- Front-batched 256-bit loads of this warp's half of the pair ----
    #pragma unroll
    for (int it = 0; it < NB; it++) {
        const int u = u0 + it * 32 + lid;
        if (u < u1) {
            const bool isL = (u < CL);
            const int  c   = isL ? u : (u - CL);
            ldg256_cs((isL ? xL : xH) + (c << 3), v[it]);
        }
    }

    // ---- exp2(x*C) with per-element mask; per-row partial sums ----
    float sL = 0.0f, sH = 0.0f;
    #pragma unroll
    for (int it = 0; it < NB; it++) {
        const int u = u0 + it * 32 + lid;
        if (u < u1) {
            const bool isL = (u < CL);
            const int  c   = isL ? u : (u - CL);
            const int  L   = isL ? LL : LH;
            const int  b   = c << 3;
            float a[8];
            #pragma unroll
            for (int e = 0; e < 8; e++)
                a[e] = (b + e < L) ? ex2_approx(v[it][e] * C) : 0.0f;
            #pragma unroll
            for (int e = 0; e < 8; e++)
                v[it][e] = a[e];
            const float t = ((a[0] + a[1]) + (a[2] + a[3]))
                          + ((a[4] + a[5]) + (a[6] + a[7]));
            if (isL) sL += t; else sH += t;
        }
    }

    // ---- Warp-reduce both partial sums ----
    #pragma unroll
    for (int o = 16; o > 0; o >>= 1) {
        sL += __shfl_xor_sync(0xffffffffu, sL, o);
        sH += __shfl_xor_sync(0xffffffffu, sH, o);
    }

    // ---- Cross-warp combine within the pair (one balanced barrier) ----
    __shared__ float sm[PAIRS_PC][2][2];
    if (lid == 0) { sm[pw][h][0] = sL; sm[pw][h][1] = sH; }
    __syncthreads();
    float invL, invH;
    {
        const float fL = sm[pw][0][0] + sm[pw][1][0];
        const float fH = sm[pw][0][1] + sm[pw][1][1];
        asm("rcp.approx.ftz.f32 %0, %1;" : "=f"(invL) : "f"(fL));
        asm("rcp.approx.ftz.f32 %0, %1;" : "=f"(invH) : "f"(fH));
    }

    // ---- Normalize + 256-bit stores of this warp's chunks ----
    #pragma unroll
    for (int it = 0; it < NB; it++) {
        const int u = u0 + it * 32 + lid;
        if (u < u1) {
            const bool isL = (u < CL);
            const int  c   = isL ? u : (u - CL);
            const float inv = isL ? invL : invH;
            float* dst = (isL ? yL : yH) + (c << 3);
            float o[8];
            #pragma unroll
            for (int e = 0; e < 8; e++)
                o[e] = v[it][e] * inv;
            stg256(dst, o);
        }
    }
}

extern "C" void kernel_launch(void* const* d_in, const int* in_sizes, int n_in,
                              void* d_out, int out_size) {
    const float* x = (const float*)d_in[0];
    float* out = (float*)d_out;

    const int rows   = out_size / SK;            // 65536
    const int pairs  = rows / 2;                 // 32768
    const int blocks = pairs / PAIRS_PC;         // 8192

    // Primary: softmax over valid chunks. Triggers PDL at entry.
    causal_softmax_prefix<<<blocks, THREADS>>>(x, out);

    // Secondary: zero-fill of masked tails, backfills primary's drain.
    cudaLaunchAttribute attrs[1];
    attrs[0].id = cudaLaunchAttributeProgrammaticStreamSerialization;
    attrs[0].val.programmaticStreamSerializationAllowed = 1;

    cudaLaunchConfig_t cfg = {};
    cfg.gridDim  = dim3(blocks, 1, 1);
    cfg.blockDim = dim3(THREADS, 1, 1);
    cfg.dynamicSmemBytes = 0;
    cfg.stream = 0;
    cfg.attrs = attrs;
    cfg.numAttrs = 1;

    cudaLaunchKernelEx(&cfg, causal_zero_tail, out);
}

// round 15
// speedup vs baseline: 1.0125x; 1.0125x over previous
#include <cuda_runtime.h>
#include <math_constants.h>

// FusedScaleMaskSoftmax: x[2,16,2048,2048] fp32 -> causal-masked softmax (last dim).
//
// R14: composition of measured-best components.
//   Kernel B (PDL primary) = R12's softmax: one row per warp, balanced row
//     pairing across warps, 256-bit ld/st, zero barriers. (R13's split-pair B
//     regressed: its dual-row addressing + barrier cost more than it saved.)
//   Kernel A (PDL secondary) = R13's zero-fill: split-pair balanced tails,
//     measured 0.8us faster than the per-row version (38.8 vs 39.6).
// PDL: B triggers completion at entry; A launches with programmatic stream
// serialization and backfills SMs during B's partial-last-wave drain.
// Disjoint chunk coverage: B writes chunks c < ceil(L/8) of each row (partial
// chunk lanes -> exact 0), A writes c >= ceil(L/8).

#define SK        2048
#define THREADS   256            // 8 warps per CTA (both kernels)
#define WARPS_PB  (THREADS / 32)
#define PAIRS_PC  4              // pairs per CTA in kernel A
#define NC        8              // 256-bit chunks per lane in kernel B
#define NA        4              // zero-fill iters in kernel A (ceil(128/32))

__device__ __forceinline__ float ex2_approx(float x) {
    float r;
    asm("ex2.approx.ftz.f32 %0, %1;" : "=f"(r) : "f"(x));
    return r;
}

__device__ __forceinline__ void ldg256_cs(const float* p, float* v) {
    unsigned u0, u1, u2, u3, u4, u5, u6, u7;
    asm volatile("ld.global.cs.v8.b32 {%0,%1,%2,%3,%4,%5,%6,%7}, [%8];"
        : "=r"(u0), "=r"(u1), "=r"(u2), "=r"(u3),
          "=r"(u4), "=r"(u5), "=r"(u6), "=r"(u7)
        : "l"(p));
    v[0] = __uint_as_float(u0); v[1] = __uint_as_float(u1);
    v[2] = __uint_as_float(u2); v[3] = __uint_as_float(u3);
    v[4] = __uint_as_float(u4); v[5] = __uint_as_float(u5);
    v[6] = __uint_as_float(u6); v[7] = __uint_as_float(u7);
}

__device__ __forceinline__ void stg256(float* p, const float* v) {
    asm volatile("st.global.v8.b32 [%0], {%1,%2,%3,%4,%5,%6,%7,%8};"
        :: "l"(p),
           "r"(__float_as_uint(v[0])), "r"(__float_as_uint(v[1])),
           "r"(__float_as_uint(v[2])), "r"(__float_as_uint(v[3])),
           "r"(__float_as_uint(v[4])), "r"(__float_as_uint(v[5])),
           "r"(__float_as_uint(v[6])), "r"(__float_as_uint(v[7]))
        : "memory");
}

// Balanced row mapping: pair j with 2047-j within each 2048-row matrix.
__device__ __forceinline__ unsigned map_row(unsigned g) {
    const unsigned q = g & (SK - 1);
    const unsigned j = q >> 1;
    const unsigned r = (q & 1u) ? (SK - 1 - j) : j;
    return (g & ~(unsigned)(SK - 1)) | r;
}

// ---------------- Kernel A: zero-fill of masked tails (PDL secondary) ----------
// Split-pair balanced: pair (j, 2047-j) has exactly 255 tail chunks; each of
// the pair's two warps writes ~half (warp0: virtual [0,128), warp1: [128,255)).
__global__ __launch_bounds__(THREADS)
void causal_zero_tail(float* __restrict__ out) {
    const int wid = threadIdx.x >> 5;
    const int lid = threadIdx.x & 31;

    const unsigned P = blockIdx.x * PAIRS_PC + (wid >> 1); // pair id
    const int h = wid & 1;

    const unsigned m = P >> 10;            // matrix 0..31
    const int j = (int)(P & 1023u);
    const unsigned rowL = (m << 11) + j;
    const unsigned rowH = (m << 11) + (SK - 1 - j);
    const int CL = (j >> 3) + 1;           // first masked chunk of rowL
    const int CH = 256 - (j >> 3);         // first masked chunk of rowH
    const int TA = 256 - CL;               // tail chunks of rowL
    const int T  = 255;                    // total tails per pair (constant)
    const int S  = 128;
    const int u0 = h ? S : 0;
    const int u1 = h ? T : S;

    float* __restrict__ yL = out + (size_t)rowL * SK;
    float* __restrict__ yH = out + (size_t)rowH * SK;
    const float z[8] = {0.f, 0.f, 0.f, 0.f, 0.f, 0.f, 0.f, 0.f};

    #pragma unroll
    for (int it = 0; it < NA; it++) {
        const int u = u0 + it * 32 + lid;
        if (u < u1) {
            const bool isL = (u < TA);
            const int  c   = isL ? (CL + u) : (CH + (u - TA));
            stg256((isL ? yL : yH) + (c << 3), z);
        }
    }
}

// ---------------- Kernel B: softmax over the causal prefix (PDL primary) ------
__global__ __launch_bounds__(THREADS)
void causal_softmax_prefix(const float* __restrict__ x,
                           float* __restrict__ out) {
    // Nothing in kernel A depends on B's output: release the PDL gate now.
    cudaTriggerProgrammaticLaunchCompletion();

    // SCALE * log2(e): fold 1/sqrt(128) into the exp2 argument.
    const float C = 0.08838834764831845f * 1.4426950408889634f;

    const int wid = threadIdx.x >> 5;
    const int lid = threadIdx.x & 31;

    const unsigned g   = blockIdx.x * WARPS_PB + wid;
    const unsigned row = map_row(g);
    const int L = (int)(row & (SK - 1)) + 1;

    const size_t base_elem = (size_t)row * SK;
    const float* __restrict__ xrow = x   + base_elem;
    float* __restrict__       yrow = out + base_elem;

    float v[NC][8];

    // Front-batched 256-bit loads of valid chunks (8c < L).
    #pragma unroll
    for (int k = 0; k < NC; k++) {
        const int b = (lid + k * 32) << 3;
        if (b < L) ldg256_cs(xrow + b, v[k]);
    }

    // exp2(x*C) with per-element tail mask (partial chunk lanes -> exact 0).
    float s = 0.0f;
    #pragma unroll
    for (int k = 0; k < NC; k++) {
        const int b = (lid + k * 32) << 3;
        if (b < L) {
            float a[8];
            #pragma unroll
            for (int e = 0; e < 8; e++)
                a[e] = (b + e < L) ? ex2_approx(v[k][e] * C) : 0.0f;
            #pragma unroll
            for (int e = 0; e < 8; e++)
                v[k][e] = a[e];
            s += ((a[0] + a[1]) + (a[2] + a[3]))
               + ((a[4] + a[5]) + (a[6] + a[7]));
        }
    }

    // Warp sum-reduce (no barriers).
    #pragma unroll
    for (int o = 16; o > 0; o >>= 1)
        s += __shfl_xor_sync(0xffffffffu, s, o);

    float inv;
    asm("rcp.approx.ftz.f32 %0, %1;" : "=f"(inv) : "f"(s));

    // Normalize + 256-bit store of valid chunks only.
    #pragma unroll
    for (int k = 0; k < NC; k++) {
        const int b = (lid + k * 32) << 3;
        if (b < L) {
            float o[8];
            #pragma unroll
            for (int e = 0; e < 8; e++)
                o[e] = v[k][e] * inv;
            stg256(yrow + b, o);
        }
    }
}

extern "C" void kernel_launch(void* const* d_in, const int* in_sizes, int n_in,
                              void* d_out, int out_size) {
    const float* x = (const float*)d_in[0];
    float* out = (float*)d_out;

    const int rows     = out_size / SK;            // 65536
    const int blocks_b = rows / WARPS_PB;          // 8192
    const int blocks_a = (rows / 2) / PAIRS_PC;    // 8192

    // Primary: softmax over valid chunks. Triggers PDL at entry.
    causal_softmax_prefix<<<blocks_b, THREADS>>>(x, out);

    // Secondary: zero-fill of masked tails, backfills primary's drain.
    cudaLaunchAttribute attrs[1];
    attrs[0].id = cudaLaunchAttributeProgrammaticStreamSerialization;
    attrs[0].val.programmaticStreamSerializationAllowed = 1;

    cudaLaunchConfig_t cfg = {};
    cfg.gridDim  = dim3(blocks_a, 1, 1);
    cfg.blockDim = dim3(THREADS, 1, 1);
    cfg.dynamicSmemBytes = 0;
    cfg.stream = 0;
    cfg.attrs = attrs;
    cfg.numAttrs = 1;

    cudaLaunchKernelEx(&cfg, causal_zero_tail, out);
}